// round 8
// baseline (speedup 1.0000x reference)
#include <cuda_runtime.h>
#include <cuda_fp16.h>
#include <cstdint>

// ---------------------------------------------------------------------------
// BaseAttention fused kernel — HMMA m16n8k16, 512 threads, strip-decoupled.
// Warp-pair (strip s = 16 rows, N-halves 0/1) runs the whole 3-layer MLP on
// its rows synchronized only by named bar.sync(1+s, 64). Query is reduced
// from layer-3 registers via shfl butterflies. Attention tail CTA-wide fp32.
// ---------------------------------------------------------------------------

#define kBatch   32768
#define kTiles   (kBatch / 4)     // 8192
#define kGrid    148
#define kThreads 512

// smem byte offsets
#define OFF_FS    0                  // [128][16] f32 raw att       8192
#define OFF_BIAS  8192               // b1,b2,b3 f32                1536
#define OFF_Q     9728               // 4x128 f32                   2048
#define OFF_P     11776              // 4x128 f32                   2048
#define OFF_LG    13824              // 128 f32                      512
#define OFF_WS    14336              // 128 f32                      512
#define OFF_MSP   14848              // 8 f32 strip mask sums (+pad)  64
#define OFF_QP    14912              // [8][128] f32 strip col sums 4096
#define OFF_PPART 19008              // [4][4][128] f32 p partials  8192
#define OFF_W1T   27200              // [128][24] f16 (k-pad)       6144
#define OFF_A     33344              // [128][136] f16 activations 34816
#define OFF_W2T   68160              // [128][136] f16             34816
#define OFF_W3T   102976             // [128][136] f16             34816
#define OFF_XR    137792             // [128][129] f32             66048
#define SMEM_BYTES 203840            // < 232448 opt-in limit

#define A_STRIDE  272                // bytes per A/W row (136 halves)
#define W1_STRIDE 48                 // bytes per W1 row (24 halves)

__device__ __half g_W1h[128 * 24];
__device__ __half g_W2h[128 * 136];
__device__ __half g_W3h[128 * 136];
__device__ float  g_MT[128 * 128];   // MT[j*128+t] = sum_k Ur[k,t]*Uq[k,j]

__device__ __forceinline__ uint32_t smem_u32(const void* p) {
    uint32_t a;
    asm("{ .reg .u64 t; cvta.to.shared.u64 t, %1; cvt.u32.u64 %0, t; }" : "=r"(a) : "l"(p));
    return a;
}

#define BAR64(S) asm volatile("bar.sync %0, 64;" :: "r"(1 + (S)) : "memory")

#define LDSM_X4(R0,R1,R2,R3,ADDR) \
    asm volatile("ldmatrix.sync.aligned.m8n8.x4.shared.b16 {%0,%1,%2,%3}, [%4];" \
                 : "=r"(R0), "=r"(R1), "=r"(R2), "=r"(R3) : "r"(ADDR))

#define MMA_16816(D_, A0,A1,A2,A3, B0,B1) \
    asm volatile("mma.sync.aligned.m16n8k16.row.col.f32.f16.f16.f32 " \
                 "{%0,%1,%2,%3}, {%4,%5,%6,%7}, {%8,%9}, {%0,%1,%2,%3};" \
                 : "+f"((D_)[0]), "+f"((D_)[1]), "+f"((D_)[2]), "+f"((D_)[3]) \
                 : "r"(A0), "r"(A1), "r"(A2), "r"(A3), "r"(B0), "r"(B1))

// ---- prep kernels ----
__global__ void pack_weights(const float* __restrict__ W1,
                             const float* __restrict__ W2,
                             const float* __restrict__ W3) {
    int i = blockIdx.x * 256 + threadIdx.x;      // 68*256 = 17408
    if (i < 128 * 136) {
        int n = i / 136, c = i % 136;
        g_W2h[i] = __float2half((c < 128) ? W2[n * 128 + c] : 0.f);
        g_W3h[i] = __float2half((c < 128) ? W3[n * 128 + c] : 0.f);
    }
    if (i < 128 * 24) {
        int n = i / 24, c = i % 24;
        g_W1h[i] = __float2half((c < 15) ? W1[n * 15 + c] : 0.f);
    }
}

__global__ void precompute_MT(const float* __restrict__ Uq, const float* __restrict__ Ur) {
    int j = blockIdx.x, t = threadIdx.x;
    float acc = 0.f;
    #pragma unroll 8
    for (int k = 0; k < 128; ++k)
        acc += Ur[k * 128 + t] * Uq[k * 128 + j];
    g_MT[j * 128 + t] = acc;
}

// K-loop GEMM: D[16 rows][64 cols] += A_strip @ W_half^T
template<int NK, int BSTRIDE>
__device__ __forceinline__ void gemm_strip(uint32_t aAddr, uint32_t bAddr, float (&d)[8][4]) {
    #pragma unroll
    for (int k = 0; k < NK; ++k) {
        uint32_t a0, a1, a2, a3;
        LDSM_X4(a0, a1, a2, a3, aAddr + k * 32);
        #pragma unroll
        for (int nt2 = 0; nt2 < 4; ++nt2) {
            uint32_t q0, q1, q2, q3;
            LDSM_X4(q0, q1, q2, q3, bAddr + nt2 * 16 * BSTRIDE + k * 32);
            MMA_16816(d[2 * nt2],     a0, a1, a2, a3, q0, q1);
            MMA_16816(d[2 * nt2 + 1], a0, a1, a2, a3, q2, q3);
        }
    }
}

extern __shared__ char smem[];

__global__ __launch_bounds__(kThreads, 1) void fused_attn_hmma(
    const float* __restrict__ obs,
    const float* __restrict__ b1, const float* __restrict__ b2, const float* __restrict__ b3,
    float* __restrict__ out)
{
    const uint32_t sb = smem_u32(smem);
    const int tid  = threadIdx.x;
    const int wid  = tid >> 5, lane = tid & 31;
    const int s    = wid >> 1;               // strip 0..7
    const int nh   = wid & 1;                // N-half 0..1
    const int r0   = s * 16;
    const int nbase = nh * 64;
    const int pairtid = tid & 63;

    // stage weights + biases
    {
        const uint4* s1 = (const uint4*)g_W1h;
        const uint4* s2 = (const uint4*)g_W2h;
        const uint4* s3 = (const uint4*)g_W3h;
        for (int i = tid; i < 384;  i += kThreads) *(uint4*)(smem + OFF_W1T + i * 16) = s1[i];
        for (int i = tid; i < 2176; i += kThreads) *(uint4*)(smem + OFF_W2T + i * 16) = s2[i];
        for (int i = tid; i < 2176; i += kThreads) *(uint4*)(smem + OFF_W3T + i * 16) = s3[i];
        if (tid < 128) {
            ((float*)(smem + OFF_BIAS))[tid]       = b1[tid];
            ((float*)(smem + OFF_BIAS))[128 + tid] = b2[tid];
            ((float*)(smem + OFF_BIAS))[256 + tid] = b3[tid];
        }
    }
    __syncthreads();

    float* fs   = (float*)(smem + OFF_FS);      // [row r][16]: fs[r*16+c]
    float* xr   = (float*)(smem + OFF_XR);
    const float* bias = (const float*)(smem + OFF_BIAS);
    float* q_s  = (float*)(smem + OFF_Q);
    float* p_s  = (float*)(smem + OFF_P);
    float* lg_s = (float*)(smem + OFF_LG);
    float* w_s  = (float*)(smem + OFF_WS);
    float* msp  = (float*)(smem + OFF_MSP);     // per-strip mask sums
    float* qp   = (float*)(smem + OFF_QP);      // per-strip col sums [8][128]
    float* pp_s = (float*)(smem + OFF_PPART);

    // ldmatrix lane addresses (tile-invariant)
    const uint32_t aAddr = sb + OFF_A + (uint32_t)(r0 + (lane & 15)) * A_STRIDE + (uint32_t)(lane >> 4) * 16;
    const uint32_t brow  = (uint32_t)((lane & 7) + ((lane >> 4) << 3));
    const uint32_t koff  = (uint32_t)(((lane >> 3) & 1) * 16);
    const uint32_t bW1   = sb + OFF_W1T + (nbase + brow) * W1_STRIDE + koff;
    const uint32_t bW2   = sb + OFF_W2T + (nbase + brow) * A_STRIDE + koff;
    const uint32_t bW3   = sb + OFF_W3T + (nbase + brow) * A_STRIDE + koff;

    // D-fragment / epilogue lane mapping
    const int rA = r0 + (lane >> 2);          // rows rA and rA+8
    const int cn = (lane & 3) * 2;            // col offset within n-tile

    // fs staging mapping: strip-local — warp pair loads its own 16 rows
    const int fs_r  = r0 + (pairtid >> 2);    // object row
    const int fs_c4 = pairtid & 3;            // float4 within row

    // ---- initial prefetch ----
    float4 pf_att, pf_aux;
    {
        const float4* o4 = (const float4*)(obs + (size_t)blockIdx.x * 4 * 576);
        pf_att = o4[(fs_r >> 5) * 144 + 8 + (fs_r & 31) * 4 + fs_c4];
        if (tid < 64) {
            const int lb = tid >> 4, j = tid & 15;
            pf_aux = (j < 8) ? o4[lb * 144 + j] : o4[lb * 144 + 136 + (j - 8)];
        }
    }

    for (int tile = blockIdx.x; tile < kTiles; tile += kGrid) {
        const int b0 = tile * 4;
        float4* out4 = (float4*)(out + (size_t)b0 * 192);

        // ---- commit prefetched att (strip-local) + aux passthrough ----
        ((float4*)fs)[fs_r * 4 + fs_c4] = pf_att;
        if (tid < 64)
            out4[(tid >> 4) * 48 + (tid & 15)] = pf_aux;
        BAR64(s);

        // ---- A1: feats fp16 (strip rows) + strip mask sum ----
        #pragma unroll
        for (int k2 = 0; k2 < 2; ++k2) {
            const int i = pairtid + 64 * k2;
            const int r = r0 + (i >> 3), cp = i & 7;
            float2 v = *(const float2*)(fs + r * 16 + 2 * cp);
            if (cp == 7) v.y = 0.f;           // col 15 = mask -> 0
            __half2 h = __floats2half2_rn(v.x, v.y);
            *(uint32_t*)(smem + OFF_A + r * A_STRIDE + cp * 4) = *(uint32_t*)&h;
        }
        if (pairtid == 0) {
            float ssum = 0.f;
            #pragma unroll
            for (int rr = 0; rr < 16; ++rr) ssum += fs[(r0 + rr) * 16 + 15];
            msp[s] = ssum;
        }
        BAR64(s);

        float d[8][4];

        // ---- layer 1 (K=16) ----
        #pragma unroll
        for (int nt = 0; nt < 8; ++nt)
            { d[nt][0] = d[nt][1] = d[nt][2] = d[nt][3] = 0.f; }
        gemm_strip<1, W1_STRIDE>(aAddr, bW1, d);
        BAR64(s);                             // pair's A1 reads done
        #pragma unroll
        for (int nt = 0; nt < 8; ++nt) {      // epi: relu(+b1) -> A fp16
            const int n = nbase + nt * 8 + cn;
            __half2 h0 = __floats2half2_rn(fmaxf(d[nt][0] + bias[n],     0.f),
                                           fmaxf(d[nt][1] + bias[n + 1], 0.f));
            __half2 h1 = __floats2half2_rn(fmaxf(d[nt][2] + bias[n],     0.f),
                                           fmaxf(d[nt][3] + bias[n + 1], 0.f));
            *(uint32_t*)(smem + OFF_A + rA * A_STRIDE + n * 2)       = *(uint32_t*)&h0;
            *(uint32_t*)(smem + OFF_A + (rA + 8) * A_STRIDE + n * 2) = *(uint32_t*)&h1;
        }
        BAR64(s);

        // ---- layer 2 (K=128) ----
        #pragma unroll
        for (int nt = 0; nt < 8; ++nt)
            { d[nt][0] = d[nt][1] = d[nt][2] = d[nt][3] = 0.f; }
        gemm_strip<8, A_STRIDE>(aAddr, bW2, d);
        BAR64(s);
        #pragma unroll
        for (int nt = 0; nt < 8; ++nt) {      // epi: relu(+b2) -> A fp16
            const int n = nbase + nt * 8 + cn;
            __half2 h0 = __floats2half2_rn(fmaxf(d[nt][0] + bias[128 + n],     0.f),
                                           fmaxf(d[nt][1] + bias[128 + n + 1], 0.f));
            __half2 h1 = __floats2half2_rn(fmaxf(d[nt][2] + bias[128 + n],     0.f),
                                           fmaxf(d[nt][3] + bias[128 + n + 1], 0.f));
            *(uint32_t*)(smem + OFF_A + rA * A_STRIDE + n * 2)       = *(uint32_t*)&h0;
            *(uint32_t*)(smem + OFF_A + (rA + 8) * A_STRIDE + n * 2) = *(uint32_t*)&h1;
        }
        BAR64(s);

        // ---- layer 3 (K=128): xr + register query reduction ----
        #pragma unroll
        for (int nt = 0; nt < 8; ++nt)
            { d[nt][0] = d[nt][1] = d[nt][2] = d[nt][3] = 0.f; }
        gemm_strip<8, A_STRIDE>(aAddr, bW3, d);
        {
            const float mkA = fs[rA * 16 + 15];
            const float mkB = fs[(rA + 8) * 16 + 15];
            float qa[8], qb[8];
            #pragma unroll
            for (int nt = 0; nt < 8; ++nt) {
                const int n = nbase + nt * 8 + cn;
                const float xA0 = (d[nt][0] + bias[256 + n])     * mkA;
                const float xA1 = (d[nt][1] + bias[256 + n + 1]) * mkA;
                const float xB0 = (d[nt][2] + bias[256 + n])     * mkB;
                const float xB1 = (d[nt][3] + bias[256 + n + 1]) * mkB;
                xr[rA * 129 + n]           = xA0;
                xr[rA * 129 + n + 1]       = xA1;
                xr[(rA + 8) * 129 + n]     = xB0;
                xr[(rA + 8) * 129 + n + 1] = xB1;
                qa[nt] = xA0 + xB0;
                qb[nt] = xA1 + xB1;
            }
            #pragma unroll
            for (int off = 4; off < 32; off <<= 1) {
                #pragma unroll
                for (int nt = 0; nt < 8; ++nt) {
                    qa[nt] += __shfl_xor_sync(0xffffffffu, qa[nt], off);
                    qb[nt] += __shfl_xor_sync(0xffffffffu, qb[nt], off);
                }
            }
            if ((lane >> 2) == 0) {           // lanes 0..3 write strip col sums
                #pragma unroll
                for (int nt = 0; nt < 8; ++nt) {
                    const int n = nbase + nt * 8 + cn;
                    qp[s * 128 + n]     = qa[nt];
                    qp[s * 128 + n + 1] = qb[nt];
                }
            }
        }
        __syncthreads();                      // all strips: xr, qp, msp ready

        // ---- prefetch next tile's obs while the tail runs ----
        {
            const int ntile = tile + kGrid;
            if (ntile < kTiles) {
                const float4* o4 = (const float4*)(obs + (size_t)ntile * 4 * 576);
                pf_att = o4[(fs_r >> 5) * 144 + 8 + (fs_r & 31) * 4 + fs_c4];
                if (tid < 64) {
                    const int lb = tid >> 4, j = tid & 15;
                    pf_aux = (j < 8) ? o4[lb * 144 + j] : o4[lb * 144 + 136 + (j - 8)];
                }
            }
        }

        // ---- attention tail (fp32, CTA-wide) ----
        const int lb = tid >> 7, dd = tid & 127;

        q_s[lb * 128 + dd] = (qp[(2 * lb) * 128 + dd] + qp[(2 * lb + 1) * 128 + dd])
                           / (msp[2 * lb] + msp[2 * lb + 1] + 1e-5f);
        __syncthreads();

        {                                     // p partials: g = j-quarter
            const int g = tid >> 7;
            float a0 = 0.f, a1 = 0.f, a2 = 0.f, a3 = 0.f;
            #pragma unroll 8
            for (int jj = 0; jj < 32; ++jj) {
                const int j = g * 32 + jj;
                const float m = g_MT[j * 128 + dd];
                a0 += m * q_s[j];
                a1 += m * q_s[128 + j];
                a2 += m * q_s[256 + j];
                a3 += m * q_s[384 + j];
            }
            pp_s[g * 512 + dd]       = a0;
            pp_s[g * 512 + 128 + dd] = a1;
            pp_s[g * 512 + 256 + dd] = a2;
            pp_s[g * 512 + 384 + dd] = a3;
        }
        __syncthreads();

        p_s[lb * 128 + dd] = pp_s[lb * 128 + dd]        + pp_s[512 + lb * 128 + dd]
                           + pp_s[1024 + lb * 128 + dd] + pp_s[1536 + lb * 128 + dd];
        __syncthreads();

        {                                     // logits (4 threads / row)
            const int row = tid >> 2, c = tid & 3;
            const int rlb = row >> 5;
            float ls = 0.f;
            #pragma unroll 8
            for (int k = 0; k < 32; ++k)
                ls += p_s[rlb * 128 + c + 4 * k] * xr[row * 129 + c + 4 * k];
            ls += __shfl_xor_sync(0xffffffffu, ls, 1);
            ls += __shfl_xor_sync(0xffffffffu, ls, 2);
            if (c == 0)
                lg_s[row] = ls + (1.f - fs[row * 16 + 15]) * -1e9f;
        }
        __syncthreads();

        if (tid < 128) {                      // softmax (one warp / batch row)
            const float l = lg_s[tid];
            float mx = l;
            #pragma unroll
            for (int sh = 16; sh > 0; sh >>= 1) mx = fmaxf(mx, __shfl_xor_sync(0xffffffffu, mx, sh));
            const float e = __expf(l - mx);
            float ssum = e;
            #pragma unroll
            for (int sh = 16; sh > 0; sh >>= 1) ssum += __shfl_xor_sync(0xffffffffu, ssum, sh);
            w_s[tid] = e / ssum;
        }
        __syncthreads();

        {                                     // out_att
            float acc = 0.f;
            #pragma unroll 8
            for (int o = 0; o < 32; ++o)
                acc += w_s[lb * 32 + o] * xr[(lb * 32 + o) * 129 + dd];
            out[(size_t)(b0 + lb) * 192 + 64 + dd] = acc;
        }
        __syncthreads();                      // protect fs/xr/qp/msp for next tile
    }
}

extern "C" void kernel_launch(void* const* d_in, const int* in_sizes, int n_in,
                              void* d_out, int out_size) {
    const float* obs = (const float*)d_in[0];
    const float* W1  = (const float*)d_in[1];
    const float* b1  = (const float*)d_in[2];
    const float* W2  = (const float*)d_in[3];
    const float* b2  = (const float*)d_in[4];
    const float* W3  = (const float*)d_in[5];
    const float* b3  = (const float*)d_in[6];
    const float* Uq  = (const float*)d_in[7];
    const float* Ur  = (const float*)d_in[8];
    float* out = (float*)d_out;

    cudaFuncSetAttribute(fused_attn_hmma,
                         cudaFuncAttributeMaxDynamicSharedMemorySize, (int)SMEM_BYTES);

    pack_weights<<<68, 256>>>(W1, W2, W3);
    precompute_MT<<<128, 128>>>(Uq, Ur);
    fused_attn_hmma<<<kGrid, kThreads, SMEM_BYTES>>>(obs, b1, b2, b3, out);
}

// round 9
// speedup vs baseline: 1.0031x; 1.0031x over previous
#include <cuda_runtime.h>
#include <cuda_fp16.h>
#include <cstdint>

// ---------------------------------------------------------------------------
// BaseAttention fused kernel — HMMA m16n8k16, 512 threads, strip-decoupled.
// Warp-pair (strip s = 16 rows, N-halves 0/1) runs the whole 3-layer MLP on
// its rows synchronized only by named bar.sync(1+s, 64). Query is reduced
// from layer-3 registers via shfl butterflies. Attention tail CTA-wide fp32.
// ---------------------------------------------------------------------------

#define kBatch   32768
#define kTiles   (kBatch / 4)     // 8192
#define kGrid    148
#define kThreads 512

// smem byte offsets
#define OFF_FS    0                  // [128][16] f32 raw att       8192
#define OFF_BIAS  8192               // b1,b2,b3 f32                1536
#define OFF_Q     9728               // 4x128 f32                   2048
#define OFF_P     11776              // 4x128 f32                   2048
#define OFF_LG    13824              // 128 f32                      512
#define OFF_WS    14336              // 128 f32                      512
#define OFF_MSP   14848              // 8 f32 strip mask sums (+pad)  64
#define OFF_QP    14912              // [8][128] f32 strip col sums 4096
#define OFF_PPART 19008              // [4][4][128] f32 p partials  8192
#define OFF_W1T   27200              // [128][24] f16 (k-pad)       6144
#define OFF_A     33344              // [128][136] f16 activations 34816
#define OFF_W2T   68160              // [128][136] f16             34816
#define OFF_W3T   102976             // [128][136] f16             34816
#define OFF_XR    137792             // [128][129] f32             66048
#define SMEM_BYTES 203840            // < 232448 opt-in limit

#define A_STRIDE  272                // bytes per A/W row (136 halves)
#define W1_STRIDE 48                 // bytes per W1 row (24 halves)

__device__ __half g_W1h[128 * 24];
__device__ __half g_W2h[128 * 136];
__device__ __half g_W3h[128 * 136];
__device__ float  g_MT[128 * 128];   // MT[j*128+t] = sum_k Ur[k,t]*Uq[k,j]

__device__ __forceinline__ uint32_t smem_u32(const void* p) {
    uint32_t a;
    asm("{ .reg .u64 t; cvta.to.shared.u64 t, %1; cvt.u32.u64 %0, t; }" : "=r"(a) : "l"(p));
    return a;
}

#define BAR64(S) asm volatile("bar.sync %0, 64;" :: "r"(1 + (S)) : "memory")

#define LDSM_X4(R0,R1,R2,R3,ADDR) \
    asm volatile("ldmatrix.sync.aligned.m8n8.x4.shared.b16 {%0,%1,%2,%3}, [%4];" \
                 : "=r"(R0), "=r"(R1), "=r"(R2), "=r"(R3) : "r"(ADDR))

#define MMA_16816(D_, A0,A1,A2,A3, B0,B1) \
    asm volatile("mma.sync.aligned.m16n8k16.row.col.f32.f16.f16.f32 " \
                 "{%0,%1,%2,%3}, {%4,%5,%6,%7}, {%8,%9}, {%0,%1,%2,%3};" \
                 : "+f"((D_)[0]), "+f"((D_)[1]), "+f"((D_)[2]), "+f"((D_)[3]) \
                 : "r"(A0), "r"(A1), "r"(A2), "r"(A3), "r"(B0), "r"(B1))

// ---- prep kernels ----
__global__ void pack_weights(const float* __restrict__ W1,
                             const float* __restrict__ W2,
                             const float* __restrict__ W3) {
    int i = blockIdx.x * 256 + threadIdx.x;      // 68*256 = 17408
    if (i < 128 * 136) {
        int n = i / 136, c = i % 136;
        g_W2h[i] = __float2half((c < 128) ? W2[n * 128 + c] : 0.f);
        g_W3h[i] = __float2half((c < 128) ? W3[n * 128 + c] : 0.f);
    }
    if (i < 128 * 24) {
        int n = i / 24, c = i % 24;
        g_W1h[i] = __float2half((c < 15) ? W1[n * 15 + c] : 0.f);
    }
}

__global__ void precompute_MT(const float* __restrict__ Uq, const float* __restrict__ Ur) {
    int j = blockIdx.x, t = threadIdx.x;
    float acc = 0.f;
    #pragma unroll 8
    for (int k = 0; k < 128; ++k)
        acc += Ur[k * 128 + t] * Uq[k * 128 + j];
    g_MT[j * 128 + t] = acc;
}

// K-loop GEMM: D[16 rows][64 cols] += A_strip @ W_half^T
template<int NK, int BSTRIDE>
__device__ __forceinline__ void gemm_strip(uint32_t aAddr, uint32_t bAddr, float (&d)[8][4]) {
    #pragma unroll
    for (int k = 0; k < NK; ++k) {
        uint32_t a0, a1, a2, a3;
        LDSM_X4(a0, a1, a2, a3, aAddr + k * 32);
        #pragma unroll
        for (int nt2 = 0; nt2 < 4; ++nt2) {
            uint32_t q0, q1, q2, q3;
            LDSM_X4(q0, q1, q2, q3, bAddr + nt2 * 16 * BSTRIDE + k * 32);
            MMA_16816(d[2 * nt2],     a0, a1, a2, a3, q0, q1);
            MMA_16816(d[2 * nt2 + 1], a0, a1, a2, a3, q2, q3);
        }
    }
}

extern __shared__ char smem[];

__global__ __launch_bounds__(kThreads, 1) void fused_attn_hmma(
    const float* __restrict__ obs,
    const float* __restrict__ b1, const float* __restrict__ b2, const float* __restrict__ b3,
    float* __restrict__ out)
{
    const uint32_t sb = smem_u32(smem);
    const int tid  = threadIdx.x;
    const int wid  = tid >> 5, lane = tid & 31;
    const int s    = wid >> 1;               // strip 0..7
    const int nh   = wid & 1;                // N-half 0..1
    const int r0   = s * 16;
    const int nbase = nh * 64;
    const int pairtid = tid & 63;

    // stage weights + biases
    {
        const uint4* s1 = (const uint4*)g_W1h;
        const uint4* s2 = (const uint4*)g_W2h;
        const uint4* s3 = (const uint4*)g_W3h;
        for (int i = tid; i < 384;  i += kThreads) *(uint4*)(smem + OFF_W1T + i * 16) = s1[i];
        for (int i = tid; i < 2176; i += kThreads) *(uint4*)(smem + OFF_W2T + i * 16) = s2[i];
        for (int i = tid; i < 2176; i += kThreads) *(uint4*)(smem + OFF_W3T + i * 16) = s3[i];
        if (tid < 128) {
            ((float*)(smem + OFF_BIAS))[tid]       = b1[tid];
            ((float*)(smem + OFF_BIAS))[128 + tid] = b2[tid];
            ((float*)(smem + OFF_BIAS))[256 + tid] = b3[tid];
        }
    }
    __syncthreads();

    float* fs   = (float*)(smem + OFF_FS);      // [row r][16]: fs[r*16+c]
    float* xr   = (float*)(smem + OFF_XR);
    const float* bias = (const float*)(smem + OFF_BIAS);
    float* q_s  = (float*)(smem + OFF_Q);
    float* p_s  = (float*)(smem + OFF_P);
    float* lg_s = (float*)(smem + OFF_LG);
    float* w_s  = (float*)(smem + OFF_WS);
    float* msp  = (float*)(smem + OFF_MSP);     // per-strip mask sums
    float* qp   = (float*)(smem + OFF_QP);      // per-strip col sums [8][128]
    float* pp_s = (float*)(smem + OFF_PPART);

    // ldmatrix lane addresses (tile-invariant)
    const uint32_t aAddr = sb + OFF_A + (uint32_t)(r0 + (lane & 15)) * A_STRIDE + (uint32_t)(lane >> 4) * 16;
    const uint32_t brow  = (uint32_t)((lane & 7) + ((lane >> 4) << 3));
    const uint32_t koff  = (uint32_t)(((lane >> 3) & 1) * 16);
    const uint32_t bW1   = sb + OFF_W1T + (nbase + brow) * W1_STRIDE + koff;
    const uint32_t bW2   = sb + OFF_W2T + (nbase + brow) * A_STRIDE + koff;
    const uint32_t bW3   = sb + OFF_W3T + (nbase + brow) * A_STRIDE + koff;

    // D-fragment / epilogue lane mapping
    const int rA = r0 + (lane >> 2);          // rows rA and rA+8
    const int cn = (lane & 3) * 2;            // col offset within n-tile

    // fs staging mapping: strip-local — warp pair loads its own 16 rows
    const int fs_r  = r0 + (pairtid >> 2);    // object row
    const int fs_c4 = pairtid & 3;            // float4 within row

    // ---- initial prefetch ----
    float4 pf_att, pf_aux;
    {
        const float4* o4 = (const float4*)(obs + (size_t)blockIdx.x * 4 * 576);
        pf_att = o4[(fs_r >> 5) * 144 + 8 + (fs_r & 31) * 4 + fs_c4];
        if (tid < 64) {
            const int lb = tid >> 4, j = tid & 15;
            pf_aux = (j < 8) ? o4[lb * 144 + j] : o4[lb * 144 + 136 + (j - 8)];
        }
    }

    for (int tile = blockIdx.x; tile < kTiles; tile += kGrid) {
        const int b0 = tile * 4;
        float4* out4 = (float4*)(out + (size_t)b0 * 192);

        // ---- commit prefetched att (strip-local) + aux passthrough ----
        ((float4*)fs)[fs_r * 4 + fs_c4] = pf_att;
        if (tid < 64)
            out4[(tid >> 4) * 48 + (tid & 15)] = pf_aux;
        BAR64(s);

        // ---- A1: feats fp16 (strip rows) + strip mask sum ----
        #pragma unroll
        for (int k2 = 0; k2 < 2; ++k2) {
            const int i = pairtid + 64 * k2;
            const int r = r0 + (i >> 3), cp = i & 7;
            float2 v = *(const float2*)(fs + r * 16 + 2 * cp);
            if (cp == 7) v.y = 0.f;           // col 15 = mask -> 0
            __half2 h = __floats2half2_rn(v.x, v.y);
            *(uint32_t*)(smem + OFF_A + r * A_STRIDE + cp * 4) = *(uint32_t*)&h;
        }
        if (pairtid == 0) {
            float ssum = 0.f;
            #pragma unroll
            for (int rr = 0; rr < 16; ++rr) ssum += fs[(r0 + rr) * 16 + 15];
            msp[s] = ssum;
        }
        BAR64(s);

        float d[8][4];

        // ---- layer 1 (K=16) ----
        #pragma unroll
        for (int nt = 0; nt < 8; ++nt)
            { d[nt][0] = d[nt][1] = d[nt][2] = d[nt][3] = 0.f; }
        gemm_strip<1, W1_STRIDE>(aAddr, bW1, d);
        BAR64(s);                             // pair's A1 reads done
        #pragma unroll
        for (int nt = 0; nt < 8; ++nt) {      // epi: relu(+b1) -> A fp16
            const int n = nbase + nt * 8 + cn;
            __half2 h0 = __floats2half2_rn(fmaxf(d[nt][0] + bias[n],     0.f),
                                           fmaxf(d[nt][1] + bias[n + 1], 0.f));
            __half2 h1 = __floats2half2_rn(fmaxf(d[nt][2] + bias[n],     0.f),
                                           fmaxf(d[nt][3] + bias[n + 1], 0.f));
            *(uint32_t*)(smem + OFF_A + rA * A_STRIDE + n * 2)       = *(uint32_t*)&h0;
            *(uint32_t*)(smem + OFF_A + (rA + 8) * A_STRIDE + n * 2) = *(uint32_t*)&h1;
        }
        BAR64(s);

        // ---- layer 2 (K=128) ----
        #pragma unroll
        for (int nt = 0; nt < 8; ++nt)
            { d[nt][0] = d[nt][1] = d[nt][2] = d[nt][3] = 0.f; }
        gemm_strip<8, A_STRIDE>(aAddr, bW2, d);
        BAR64(s);
        #pragma unroll
        for (int nt = 0; nt < 8; ++nt) {      // epi: relu(+b2) -> A fp16
            const int n = nbase + nt * 8 + cn;
            __half2 h0 = __floats2half2_rn(fmaxf(d[nt][0] + bias[128 + n],     0.f),
                                           fmaxf(d[nt][1] + bias[128 + n + 1], 0.f));
            __half2 h1 = __floats2half2_rn(fmaxf(d[nt][2] + bias[128 + n],     0.f),
                                           fmaxf(d[nt][3] + bias[128 + n + 1], 0.f));
            *(uint32_t*)(smem + OFF_A + rA * A_STRIDE + n * 2)       = *(uint32_t*)&h0;
            *(uint32_t*)(smem + OFF_A + (rA + 8) * A_STRIDE + n * 2) = *(uint32_t*)&h1;
        }
        BAR64(s);

        // ---- layer 3 (K=128): xr + register query reduction ----
        #pragma unroll
        for (int nt = 0; nt < 8; ++nt)
            { d[nt][0] = d[nt][1] = d[nt][2] = d[nt][3] = 0.f; }
        gemm_strip<8, A_STRIDE>(aAddr, bW3, d);
        {
            const float mkA = fs[rA * 16 + 15];
            const float mkB = fs[(rA + 8) * 16 + 15];
            float qa[8], qb[8];
            #pragma unroll
            for (int nt = 0; nt < 8; ++nt) {
                const int n = nbase + nt * 8 + cn;
                const float xA0 = (d[nt][0] + bias[256 + n])     * mkA;
                const float xA1 = (d[nt][1] + bias[256 + n + 1]) * mkA;
                const float xB0 = (d[nt][2] + bias[256 + n])     * mkB;
                const float xB1 = (d[nt][3] + bias[256 + n + 1]) * mkB;
                xr[rA * 129 + n]           = xA0;
                xr[rA * 129 + n + 1]       = xA1;
                xr[(rA + 8) * 129 + n]     = xB0;
                xr[(rA + 8) * 129 + n + 1] = xB1;
                qa[nt] = xA0 + xB0;
                qb[nt] = xA1 + xB1;
            }
            #pragma unroll
            for (int off = 4; off < 32; off <<= 1) {
                #pragma unroll
                for (int nt = 0; nt < 8; ++nt) {
                    qa[nt] += __shfl_xor_sync(0xffffffffu, qa[nt], off);
                    qb[nt] += __shfl_xor_sync(0xffffffffu, qb[nt], off);
                }
            }
            if ((lane >> 2) == 0) {           // lanes 0..3 write strip col sums
                #pragma unroll
                for (int nt = 0; nt < 8; ++nt) {
                    const int n = nbase + nt * 8 + cn;
                    qp[s * 128 + n]     = qa[nt];
                    qp[s * 128 + n + 1] = qb[nt];
                }
            }
        }
        __syncthreads();                      // all strips: xr, qp, msp ready

        // ---- prefetch next tile's obs while the tail runs ----
        {
            const int ntile = tile + kGrid;
            if (ntile < kTiles) {
                const float4* o4 = (const float4*)(obs + (size_t)ntile * 4 * 576);
                pf_att = o4[(fs_r >> 5) * 144 + 8 + (fs_r & 31) * 4 + fs_c4];
                if (tid < 64) {
                    const int lb = tid >> 4, j = tid & 15;
                    pf_aux = (j < 8) ? o4[lb * 144 + j] : o4[lb * 144 + 136 + (j - 8)];
                }
            }
        }

        // ---- attention tail (fp32, CTA-wide) ----
        const int lb = tid >> 7, dd = tid & 127;

        q_s[lb * 128 + dd] = (qp[(2 * lb) * 128 + dd] + qp[(2 * lb + 1) * 128 + dd])
                           / (msp[2 * lb] + msp[2 * lb + 1] + 1e-5f);
        __syncthreads();

        {                                     // p partials: g = j-quarter
            const int g = tid >> 7;
            float a0 = 0.f, a1 = 0.f, a2 = 0.f, a3 = 0.f;
            #pragma unroll 8
            for (int jj = 0; jj < 32; ++jj) {
                const int j = g * 32 + jj;
                const float m = g_MT[j * 128 + dd];
                a0 += m * q_s[j];
                a1 += m * q_s[128 + j];
                a2 += m * q_s[256 + j];
                a3 += m * q_s[384 + j];
            }
            pp_s[g * 512 + dd]       = a0;
            pp_s[g * 512 + 128 + dd] = a1;
            pp_s[g * 512 + 256 + dd] = a2;
            pp_s[g * 512 + 384 + dd] = a3;
        }
        __syncthreads();

        p_s[lb * 128 + dd] = pp_s[lb * 128 + dd]        + pp_s[512 + lb * 128 + dd]
                           + pp_s[1024 + lb * 128 + dd] + pp_s[1536 + lb * 128 + dd];
        __syncthreads();

        {                                     // logits (4 threads / row)
            const int row = tid >> 2, c = tid & 3;
            const int rlb = row >> 5;
            float ls = 0.f;
            #pragma unroll 8
            for (int k = 0; k < 32; ++k)
                ls += p_s[rlb * 128 + c + 4 * k] * xr[row * 129 + c + 4 * k];
            ls += __shfl_xor_sync(0xffffffffu, ls, 1);
            ls += __shfl_xor_sync(0xffffffffu, ls, 2);
            if (c == 0)
                lg_s[row] = ls + (1.f - fs[row * 16 + 15]) * -1e9f;
        }
        __syncthreads();

        if (tid < 128) {                      // softmax (one warp / batch row)
            const float l = lg_s[tid];
            float mx = l;
            #pragma unroll
            for (int sh = 16; sh > 0; sh >>= 1) mx = fmaxf(mx, __shfl_xor_sync(0xffffffffu, mx, sh));
            const float e = __expf(l - mx);
            float ssum = e;
            #pragma unroll
            for (int sh = 16; sh > 0; sh >>= 1) ssum += __shfl_xor_sync(0xffffffffu, ssum, sh);
            w_s[tid] = e / ssum;
        }
        __syncthreads();

        {                                     // out_att
            float acc = 0.f;
            #pragma unroll 8
            for (int o = 0; o < 32; ++o)
                acc += w_s[lb * 32 + o] * xr[(lb * 32 + o) * 129 + dd];
            out[(size_t)(b0 + lb) * 192 + 64 + dd] = acc;
        }
        __syncthreads();                      // protect fs/xr/qp/msp for next tile
    }
}

extern "C" void kernel_launch(void* const* d_in, const int* in_sizes, int n_in,
                              void* d_out, int out_size) {
    const float* obs = (const float*)d_in[0];
    const float* W1  = (const float*)d_in[1];
    const float* b1  = (const float*)d_in[2];
    const float* W2  = (const float*)d_in[3];
    const float* b2  = (const float*)d_in[4];
    const float* W3  = (const float*)d_in[5];
    const float* b3  = (const float*)d_in[6];
    const float* Uq  = (const float*)d_in[7];
    const float* Ur  = (const float*)d_in[8];
    float* out = (float*)d_out;

    cudaFuncSetAttribute(fused_attn_hmma,
                         cudaFuncAttributeMaxDynamicSharedMemorySize, (int)SMEM_BYTES);

    pack_weights<<<68, 256>>>(W1, W2, W3);
    precompute_MT<<<128, 128>>>(Uq, Ur);
    fused_attn_hmma<<<kGrid, kThreads, SMEM_BYTES>>>(obs, b1, b2, b3, out);
}